// round 3
// baseline (speedup 1.0000x reference)
#include <cuda_runtime.h>
#include <cstdint>

#define D 64
#define MAX_NODES 100000

// scratch: per-node neighbor embedding sums (no cudaMalloc allowed)
__device__ float g_nbr[(size_t)MAX_NODES * D];

// ---------------------------------------------------------------------------
// Kernel 1: zero nbr scratch + zero d_out (poisoned by harness)
// ---------------------------------------------------------------------------
__global__ void zero_kernel(float* __restrict__ out, int n_vec4) {
    int i = blockIdx.x * blockDim.x + threadIdx.x;
    float4 z = make_float4(0.f, 0.f, 0.f, 0.f);
    if (i < n_vec4) reinterpret_cast<float4*>(g_nbr)[i] = z;
    if (i < D / 4)  reinterpret_cast<float4*>(out)[i]   = z;
}

// ---------------------------------------------------------------------------
// Kernel 2: edge scatter  nbr[dst] += emb[src]
// 16 lanes per edge, one float4 each -> 256B coalesced gather per edge,
// vectorized no-return reduction (REDG.128) into the L2-resident nbr buffer.
// Grid-stride so each thread handles several edges (MLP hides L2 latency).
// ---------------------------------------------------------------------------
#define SCAT_BLOCKS 4736   // 148 SMs * 32 warps... (4736 blocks * 256 thr)

__global__ __launch_bounds__(256) void scatter_kernel(
    const float* __restrict__ emb,
    const int* __restrict__ src,
    const int* __restrict__ dst,
    int n_items) {
    int stride = gridDim.x * blockDim.x;
    for (int i = blockIdx.x * blockDim.x + threadIdx.x; i < n_items; i += stride) {
        int e = i >> 4;
        int c = i & 15;
        int s = __ldg(src + e);
        int d = __ldg(dst + e);
        float4 v = __ldg(reinterpret_cast<const float4*>(emb) + (size_t)s * 16 + c);
        float* p = g_nbr + (size_t)d * D + c * 4;
        asm volatile("red.global.add.v4.f32 [%0], {%1,%2,%3,%4};"
                     :: "l"(p), "f"(v.x), "f"(v.y), "f"(v.z), "f"(v.w)
                     : "memory");
    }
}

// ---------------------------------------------------------------------------
// Kernel 3: fused MLP + relu + graph-sum
//   out += sum_v relu(feat[v] @ W1^T + b1 + nbr[v] @ W2^T + b2)
// Block = 256 threads: 16 node-slots x 16 output-groups (4 outs each, float4).
// W1^T / W2^T staged transposed in smem (conflict-free LDS.128 over outputs);
// feat/nbr node rows staged with pad-4 rows to avoid slot bank conflicts.
// ---------------------------------------------------------------------------
#define TILE 16
#define MLP_BLOCKS 592   // 148 SMs * 4 resident CTAs

__global__ __launch_bounds__(256) void mlp_kernel(
    const float* __restrict__ feat,
    const float* __restrict__ W1,
    const float* __restrict__ b1,
    const float* __restrict__ W2,
    const float* __restrict__ b2,
    float* __restrict__ out,
    int n_nodes) {

    __shared__ float W1t[D * D];        // [k][o]
    __shared__ float W2t[D * D];        // [k][o]
    __shared__ float bc[D];             // b1 + b2
    __shared__ float fS[TILE][D + 4];   // padded rows
    __shared__ float nS[TILE][D + 4];
    __shared__ float redbuf[TILE][D];

    const int t = threadIdx.x;

    // load + transpose weights once per block
    for (int i = t; i < D * D; i += 256) {
        int o = i >> 6, k = i & 63;
        W1t[k * D + o] = W1[i];
        W2t[k * D + o] = W2[i];
    }
    if (t < D) bc[t] = b1[t] + b2[t];

    const int slot = t >> 4;       // 0..15 node slot
    const int og   = t & 15;       // output group: outs og*4 .. og*4+3
    float4 gsum = make_float4(0.f, 0.f, 0.f, 0.f);

    const int n_tiles = (n_nodes + TILE - 1) / TILE;
    for (int tile = blockIdx.x; tile < n_tiles; tile += gridDim.x) {
        const int base = tile * TILE;
        __syncthreads();  // also covers weight-load on first iteration
        // stage 16 node rows of feat and nbr (1024 floats each, 4/thread)
        #pragma unroll
        for (int j = 0; j < 4; j++) {
            int idx = t + j * 256;          // 0..1023
            int r = idx >> 6, k = idx & 63;
            int v = base + r;
            float fv = 0.f, nv = 0.f;
            if (v < n_nodes) {
                fv = feat[(size_t)v * D + k];
                nv = g_nbr[(size_t)v * D + k];
            }
            fS[r][k] = fv;
            nS[r][k] = nv;
        }
        __syncthreads();

        float4 acc = reinterpret_cast<const float4*>(bc)[og];
        #pragma unroll
        for (int k = 0; k < D; k++) {
            float f  = fS[slot][k];
            float nn = nS[slot][k];
            float4 w1 = reinterpret_cast<const float4*>(W1t + k * D)[og];
            float4 w2 = reinterpret_cast<const float4*>(W2t + k * D)[og];
            acc.x += f * w1.x + nn * w2.x;
            acc.y += f * w1.y + nn * w2.y;
            acc.z += f * w1.z + nn * w2.z;
            acc.w += f * w1.w + nn * w2.w;
        }
        if (base + slot < n_nodes) {
            gsum.x += fmaxf(acc.x, 0.f);
            gsum.y += fmaxf(acc.y, 0.f);
            gsum.z += fmaxf(acc.z, 0.f);
            gsum.w += fmaxf(acc.w, 0.f);
        }
    }

    // reduce per-block: 16 slots -> 1, then atomic into d_out
    reinterpret_cast<float4*>(&redbuf[slot][0])[og] = gsum;
    __syncthreads();
    if (t < D) {
        float s = 0.f;
        #pragma unroll
        for (int r = 0; r < TILE; r++) s += redbuf[r][t];
        atomicAdd(out + t, s);
    }
}

// ---------------------------------------------------------------------------
// launch
// inputs (metadata order): feat, emb, W1, b1, W2, b2, edge_src, edge_dst
// ---------------------------------------------------------------------------
extern "C" void kernel_launch(void* const* d_in, const int* in_sizes, int n_in,
                              void* d_out, int out_size) {
    (void)n_in; (void)out_size;
    const float* feat = (const float*)d_in[0];
    const float* emb  = (const float*)d_in[1];
    const float* W1   = (const float*)d_in[2];
    const float* b1   = (const float*)d_in[3];
    const float* W2   = (const float*)d_in[4];
    const float* b2   = (const float*)d_in[5];
    const int* esrc   = (const int*)d_in[6];
    const int* edst   = (const int*)d_in[7];
    float* out        = (float*)d_out;

    const int n_nodes = in_sizes[0] / D;
    const int n_edges = in_sizes[6];

    // 1) zero scratch + output
    {
        int n_vec4 = n_nodes * (D / 4);
        int blocks = (n_vec4 + 255) / 256;
        zero_kernel<<<blocks, 256>>>(out, n_vec4);
    }
    // 2) scatter
    {
        int n_items = n_edges * 16;
        scatter_kernel<<<SCAT_BLOCKS, 256>>>(emb, esrc, edst, n_items);
    }
    // 3) MLP + reduce
    mlp_kernel<<<MLP_BLOCKS, 256>>>(feat, W1, b1, W2, b2, out, n_nodes);
}

// round 4
// speedup vs baseline: 3.0451x; 3.0451x over previous
#include <cuda_runtime.h>
#include <cuda_bf16.h>
#include <cstdint>

#define D 64
#define MAX_NODES 100000

// scratch (no cudaMalloc allowed): bf16 neighbor sums + bf16 copy of emb.
// 16B alignment required for uint4 loads / RED.128.
__device__ __align__(16) __nv_bfloat16 g_nbr[(size_t)MAX_NODES * D];
__device__ __align__(16) __nv_bfloat16 g_embh[(size_t)MAX_NODES * D];

static __device__ __forceinline__ uint32_t pack_bf2(float a, float b) {
    __nv_bfloat162 h;
    h.x = __float2bfloat16(a);
    h.y = __float2bfloat16(b);
    return *reinterpret_cast<uint32_t*>(&h);
}
static __device__ __forceinline__ void unpack_bf2(uint32_t u, float& a, float& b) {
    __nv_bfloat162 h = *reinterpret_cast<__nv_bfloat162*>(&u);
    a = __bfloat162float(h.x);
    b = __bfloat162float(h.y);
}

// ---------------------------------------------------------------------------
// Kernel 1: prep — convert emb fp32 -> bf16 scratch, zero g_nbr, zero d_out.
// One thread per float4 group of emb (n_nodes*16 groups).
// ---------------------------------------------------------------------------
__global__ __launch_bounds__(256) void prep_kernel(const float* __restrict__ emb,
                                                   float* __restrict__ out,
                                                   int n_grp) {
    int i = blockIdx.x * blockDim.x + threadIdx.x;
    if (i < n_grp) {
        float4 v = __ldg(reinterpret_cast<const float4*>(emb) + i);
        uint2 pk;
        pk.x = pack_bf2(v.x, v.y);
        pk.y = pack_bf2(v.z, v.w);
        reinterpret_cast<uint2*>(g_embh)[i] = pk;
        reinterpret_cast<uint2*>(g_nbr)[i] = make_uint2(0u, 0u);
    }
    if (i < D / 4) reinterpret_cast<float4*>(out)[i] = make_float4(0.f, 0.f, 0.f, 0.f);
}

// ---------------------------------------------------------------------------
// Kernel 2: edge scatter  nbr[dst] += emb_bf16[src]
// 8 lanes per edge: each gathers 16B (8 bf16) of the 128B row and issues one
// red.global.add.noftz.v4.bf16x2 (16B) into the L2-resident nbr buffer.
// Half the bytes AND half the atomic-op count of the fp32 version.
// ---------------------------------------------------------------------------
#define SCAT_BLOCKS 4736

__global__ __launch_bounds__(256) void scatter_kernel(
    const int* __restrict__ src,
    const int* __restrict__ dst,
    int n_items) {
    int stride = gridDim.x * blockDim.x;
    for (int i = blockIdx.x * blockDim.x + threadIdx.x; i < n_items; i += stride) {
        int e = i >> 3;
        int c = i & 7;
        int s = __ldg(src + e);
        int d = __ldg(dst + e);
        uint4 v = *(reinterpret_cast<const uint4*>(g_embh) + (size_t)s * 8 + c);
        __nv_bfloat16* p = g_nbr + (size_t)d * D + c * 8;
        asm volatile("red.global.add.noftz.v4.bf16x2 [%0], {%1,%2,%3,%4};"
                     :: "l"(p), "r"(v.x), "r"(v.y), "r"(v.z), "r"(v.w)
                     : "memory");
    }
}

// ---------------------------------------------------------------------------
// Kernel 3: fused MLP + relu + graph-sum
//   out += sum_v relu(feat[v] @ W1^T + b1 + nbr[v] @ W2^T + b2)
// TILE=64 nodes per CTA iteration; thread = 4 nodes x 4 outputs (register
// blocked) with k-vectorized float4 activation loads -> FFMA-bound
// (32 FMA instr vs ~8 smem wavefronts per warp per k).
// Dynamic smem 64KB: W1t[64][64] + W2t[64][64] (transposed, fp32) +
// fS[64][64] + nS[64][64].
// ---------------------------------------------------------------------------
#define MLP_BLOCKS 444   // 148 SMs * 3 resident CTAs (64KB smem each)
#define MLP_SMEM   65536

__global__ __launch_bounds__(256) void mlp_kernel(
    const float* __restrict__ feat,
    const float* __restrict__ W1,
    const float* __restrict__ b1,
    const float* __restrict__ W2,
    const float* __restrict__ b2,
    float* __restrict__ out,
    int n_nodes) {

    extern __shared__ float sm[];
    float* W1t = sm;            // [k][o] 4096 floats
    float* W2t = sm + 4096;     // [k][o]
    float* fS  = sm + 8192;     // [node][k] stride 64
    float* nS  = sm + 12288;

    const int t = threadIdx.x;

    // load + transpose weights once per block
    for (int i = t; i < D * D; i += 256) {
        int o = i >> 6, k = i & 63;
        W1t[k * D + o] = W1[i];
        W2t[k * D + o] = W2[i];
    }

    const int og   = t & 15;      // 4 outputs: og*4 .. og*4+3
    const int slot = t >> 4;      // 4 nodes:  slot*4 .. slot*4+3

    float4 bsum;
    {
        float4 v1 = __ldg(reinterpret_cast<const float4*>(b1) + og);
        float4 v2 = __ldg(reinterpret_cast<const float4*>(b2) + og);
        bsum = make_float4(v1.x + v2.x, v1.y + v2.y, v1.z + v2.z, v1.w + v2.w);
    }

    float4 gsum = make_float4(0.f, 0.f, 0.f, 0.f);
    const int n_tiles = (n_nodes + 63) >> 6;

    for (int tile = blockIdx.x; tile < n_tiles; tile += gridDim.x) {
        const int base = tile << 6;
        __syncthreads();   // protects previous iteration's reads (and weight load, iter 0)

        // stage feat: 64 rows x 16 float4 = 1024 float4
        #pragma unroll
        for (int j = 0; j < 4; j++) {
            int idx = t + j * 256;
            int row = idx >> 4;
            int v = base + row;
            float4 val = (v < n_nodes)
                ? __ldg(reinterpret_cast<const float4*>(feat) + (size_t)v * 16 + (idx & 15))
                : make_float4(0.f, 0.f, 0.f, 0.f);
            reinterpret_cast<float4*>(fS)[idx] = val;
        }
        // stage nbr (bf16 -> fp32): 64 rows x 8 uint4 = 512 uint4
        #pragma unroll
        for (int j = 0; j < 2; j++) {
            int p = t + j * 256;
            int row = p >> 3;
            int v = base + row;
            float4 lo = make_float4(0.f, 0.f, 0.f, 0.f);
            float4 hi = lo;
            if (v < n_nodes) {
                uint4 u = *(reinterpret_cast<const uint4*>(g_nbr) + (size_t)v * 8 + (p & 7));
                unpack_bf2(u.x, lo.x, lo.y);
                unpack_bf2(u.y, lo.z, lo.w);
                unpack_bf2(u.z, hi.x, hi.y);
                unpack_bf2(u.w, hi.z, hi.w);
            }
            reinterpret_cast<float4*>(nS)[p * 2 + 0] = lo;
            reinterpret_cast<float4*>(nS)[p * 2 + 1] = hi;
        }
        __syncthreads();

        float4 acc[4];
        #pragma unroll
        for (int n = 0; n < 4; n++) acc[n] = bsum;

        #pragma unroll 4
        for (int k4 = 0; k4 < 16; k4++) {
            float fa[4][4], na[4][4];
            #pragma unroll
            for (int n = 0; n < 4; n++) {
                float4 fv = reinterpret_cast<const float4*>(fS + (slot * 4 + n) * D)[k4];
                float4 nv = reinterpret_cast<const float4*>(nS + (slot * 4 + n) * D)[k4];
                fa[n][0] = fv.x; fa[n][1] = fv.y; fa[n][2] = fv.z; fa[n][3] = fv.w;
                na[n][0] = nv.x; na[n][1] = nv.y; na[n][2] = nv.z; na[n][3] = nv.w;
            }
            #pragma unroll
            for (int kk = 0; kk < 4; kk++) {
                int k = k4 * 4 + kk;
                float4 w1 = reinterpret_cast<const float4*>(W1t + k * D)[og];
                float4 w2 = reinterpret_cast<const float4*>(W2t + k * D)[og];
                #pragma unroll
                for (int n = 0; n < 4; n++) {
                    acc[n].x += fa[n][kk] * w1.x + na[n][kk] * w2.x;
                    acc[n].y += fa[n][kk] * w1.y + na[n][kk] * w2.y;
                    acc[n].z += fa[n][kk] * w1.z + na[n][kk] * w2.z;
                    acc[n].w += fa[n][kk] * w1.w + na[n][kk] * w2.w;
                }
            }
        }

        // relu + accumulate into per-thread graph sum (bounds per node)
        #pragma unroll
        for (int n = 0; n < 4; n++) {
            if (base + slot * 4 + n < n_nodes) {
                gsum.x += fmaxf(acc[n].x, 0.f);
                gsum.y += fmaxf(acc[n].y, 0.f);
                gsum.z += fmaxf(acc[n].z, 0.f);
                gsum.w += fmaxf(acc[n].w, 0.f);
            }
        }
    }

    // block reduction: 16 slots -> 1, then atomic into d_out
    __syncthreads();
    float* red = fS;   // alias staging area: [16][64]
    reinterpret_cast<float4*>(red + slot * D)[og] = gsum;
    __syncthreads();
    if (t < D) {
        float s = 0.f;
        #pragma unroll
        for (int r = 0; r < 16; r++) s += red[r * D + t];
        atomicAdd(out + t, s);
    }
}

// ---------------------------------------------------------------------------
// launch
// inputs (metadata order): feat, emb, W1, b1, W2, b2, edge_src, edge_dst
// ---------------------------------------------------------------------------
extern "C" void kernel_launch(void* const* d_in, const int* in_sizes, int n_in,
                              void* d_out, int out_size) {
    (void)n_in; (void)out_size;
    const float* feat = (const float*)d_in[0];
    const float* emb  = (const float*)d_in[1];
    const float* W1   = (const float*)d_in[2];
    const float* b1   = (const float*)d_in[3];
    const float* W2   = (const float*)d_in[4];
    const float* b2   = (const float*)d_in[5];
    const int* esrc   = (const int*)d_in[6];
    const int* edst   = (const int*)d_in[7];
    float* out        = (float*)d_out;

    const int n_nodes = in_sizes[0] / D;
    const int n_edges = in_sizes[6];

    // 1) prep: emb->bf16, zero scratch + out
    {
        int n_grp = n_nodes * (D / 4);
        int blocks = (n_grp + 255) / 256;
        prep_kernel<<<blocks, 256>>>(emb, out, n_grp);
    }
    // 2) scatter (bf16 RED.128)
    {
        int n_items = n_edges * 8;
        scatter_kernel<<<SCAT_BLOCKS, 256>>>(esrc, edst, n_items);
    }
    // 3) MLP + relu + graph reduce
    static int smem_set = 0;
    if (!smem_set) {
        cudaFuncSetAttribute(mlp_kernel, cudaFuncAttributeMaxDynamicSharedMemorySize, MLP_SMEM);
        smem_set = 1;
    }
    mlp_kernel<<<MLP_BLOCKS, 256, MLP_SMEM>>>(feat, W1, b1, W2, b2, out, n_nodes);
}